// round 13
// baseline (speedup 1.0000x reference)
#include <cuda_runtime.h>
#include <cuda_fp16.h>

#define Bn 256
#define Cn 3
#define Hn 256
#define Wn 256

// Scratch (static device globals — allocation-free per harness rules)
__device__ __half g_buf[Bn * Cn * Hn * Wn]; // rotated+flipped intermediate (fp16, 96 MiB)
__device__ float g_Wy[Bn * Hn];             // per-batch crop row weight vectors
__device__ float g_Wx[Bn * Wn];
__device__ int   g_cy0[Bn * Hn];            // crop mapping: floor coord + frac
__device__ float g_cfy[Bn * Hn];
__device__ int   g_cx0[Bn * Wn];
__device__ float g_cfx[Bn * Wn];
__device__ float g_cth[Bn], g_sth[Bn], g_xsign[Bn];
__device__ float g_partial[Bn * 64];        // per-block weighted partial sums
__device__ int   g_done[Bn];                // per-image k1-completion counters

// ---------------------------------------------------------------------------
// K0: per-batch parameters. Wy/Wx built by PARALLEL windowed gather: the crop
// map is monotone with stride in (0.797, 1] and clipping never binds
// (start >= 0, start+255 <= sz-1), so bin t only receives from y with
// sy0[y] in {t-1, t} — a <=4-wide window; we scan 9 padded values in
// ascending y (bit-identical accumulation order to the serial scatter).
// Also zeroes g_done for the fused kernel.
// ---------------------------------------------------------------------------
__global__ void __launch_bounds__(256) k0_params(
    const float* __restrict__ rt, const float* __restrict__ rf,
    const float* __restrict__ rsz, const float* __restrict__ rsh)
{
    int b = blockIdx.x;
    int t = threadIdx.x;

    __shared__ float s_start[2], s_sizem1[2];
    __shared__ int   sy0[256];  __shared__ float sfy[256];
    __shared__ int   sx0[256];  __shared__ float sfx[256];

    if (t == 0) {
        float th = (rt[b] * 2.0f - 1.0f) * 3.14159265358979323846f;
        g_cth[b] = cosf(th);
        g_sth[b] = sinf(th);
        g_xsign[b] = (rf[b] > 0.5f) ? -1.0f : 1.0f;
        g_done[b] = 0;
    }
    if (t < 2) {
        // sizes = round(h*(r/4+1) - 0.5); *256 exact, no contraction risk
        float r  = rsz[b * 2 + t];
        float sz = rintf((r * 0.25f + 1.0f) * 256.0f - 0.5f);
        float maxsh = sz - 256.0f;
        float rng   = maxsh - 1e-5f;
        // shifts = round(rand*rng - rng/2); forbid fma contraction (round edge)
        float sh = rintf(__fsub_rn(__fmul_rn(rsh[b * 2 + t], rng), rng * 0.5f));
        s_start[t]  = floorf(maxsh * 0.5f) + sh;
        s_sizem1[t] = sz - 1.0f;
    }
    __syncthreads();

    {
        float sy = __fdiv_rn(__fmul_rn(s_start[0] + (float)t, 255.0f), s_sizem1[0]);
        sy = fminf(fmaxf(sy, 0.0f), 255.0f);
        float y0 = floorf(sy);
        sy0[t] = (int)y0;  sfy[t] = sy - y0;

        float sx = __fdiv_rn(__fmul_rn(s_start[1] + (float)t, 255.0f), s_sizem1[1]);
        sx = fminf(fmaxf(sx, 0.0f), 255.0f);
        float x0 = floorf(sx);
        sx0[t] = (int)x0;  sfx[t] = sx - x0;
    }
    __syncthreads();

    float Wy = 0.0f;
    {
        float base = (float)(t - 1) * s_sizem1[0] * (1.0f / 255.0f) - s_start[0];
        int yl = max((int)floorf(base) - 2, 0);
        int yh = min(yl + 8, 255);
        for (int y = yl; y <= yh; y++) {
            int i = sy0[y]; float f = sfy[y];
            if (i == t - 1) Wy += f;
            if (i == t)     Wy += 1.0f - f;
        }
    }
    float Wx = 0.0f;
    {
        float base = (float)(t - 1) * s_sizem1[1] * (1.0f / 255.0f) - s_start[1];
        int xl = max((int)floorf(base) - 2, 0);
        int xh = min(xl + 8, 255);
        for (int x = xl; x <= xh; x++) {
            int i = sx0[x]; float f = sfx[x];
            if (i == t - 1) Wx += f;
            if (i == t)     Wx += 1.0f - f;
        }
    }

    int o = (b << 8) + t;
    g_cy0[o] = sy0[t];  g_cfy[o] = sfy[t];
    g_cx0[o] = sx0[t];  g_cfx[o] = sfx[t];
    g_Wy[o]  = Wy;      g_Wx[o]  = Wx;
}

// ---------------------------------------------------------------------------
// KMAIN: fused k1 (rotate) + k2 (crop+color) in ONE launch.
// Block order is pipelined over 4-image groups G0..G63:
//   slot 0: k1 G0 | slot 1: k1 G1 | slot 2+2i: k2 Gi | slot 3+2i: k1 G(2+i)
//   | slots 126,127: k2 G62, G63.
// Every k2 block depends only on blocks >=768 earlier in dispatch order;
// k1 blocks never wait -> progress guaranteed under in-order dispatch.
// Sync: k1 blocks __threadfence + atomicAdd(g_done[b]); k2 blocks
// acquire-spin (nanosleep backoff) until g_done[b]==64. buf stays L2-hot.
// ---------------------------------------------------------------------------
__global__ void __launch_bounds__(256) kmain(
    const float* __restrict__ img,
    const float* __restrict__ rdelta, const float* __restrict__ rm1,
    const float* __restrict__ rm2, float* __restrict__ out)
{
    __shared__ __align__(16) char smraw[28256];

    int blk  = blockIdx.x;
    int slot = blk >> 8;            // 0..127
    int sub  = blk & 255;
    int tid  = threadIdx.x;

    int role, grp;                  // role 1 = rotate, 2 = crop+color
    if (slot == 0)        { role = 1; grp = 0; }
    else if (slot == 1)   { role = 1; grp = 1; }
    else if (slot >= 126) { role = 2; grp = slot - 64; }          // 62, 63
    else {
        int i = slot - 2;
        if (i & 1) { role = 1; grp = 2 + (i >> 1); }
        else       { role = 2; grp = i >> 1; }
    }
    int b    = (grp << 2) + (sub >> 6);
    int tile = sub & 63;
    int bi   = b * 3;

    if (role == 1) {
        // ================= k1: rotation + flip + zero-pad -> fp16 buf ======
        float2* s01 = (float2*)smraw;                   // 2352 float2
        float*  s2  = (float*)(smraw + 18816);          // 2352 float
        float*  red = (float*)(smraw + 28224);          // 8 float

        int tx0 = (tile & 7) << 5;
        int ty0 = (tile >> 3) << 5;

        float cth = g_cth[b], sth = g_sth[b], xsg = g_xsign[b];

        float minx = 1e30f, maxx = -1e30f, miny = 1e30f, maxy = -1e30f;
        {
            float xnA = ((float)(2 * tx0 + 1)        * (1.0f / 256.0f) - 1.0f) * xsg;
            float xnB = ((float)(2 * (tx0 + 31) + 1) * (1.0f / 256.0f) - 1.0f) * xsg;
            float ynA =  (float)(2 * ty0 + 1)        * (1.0f / 256.0f) - 1.0f;
            float ynB =  (float)(2 * (ty0 + 31) + 1) * (1.0f / 256.0f) - 1.0f;
            #pragma unroll
            for (int i = 0; i < 4; i++) {
                float xn = (i & 1) ? xnB : xnA;
                float yn = (i & 2) ? ynB : ynA;
                float xp = cth * xn - sth * yn;
                float yp = sth * xn + cth * yn;
                float ix = ((xp + 1.0f) * 256.0f - 1.0f) * 0.5f;
                float iy = ((yp + 1.0f) * 256.0f - 1.0f) * 0.5f;
                minx = fminf(minx, ix); maxx = fmaxf(maxx, ix);
                miny = fminf(miny, iy); maxy = fmaxf(maxy, iy);
            }
        }
        // bbox clamped into image on BOTH ends; bx0 even; non-degenerate.
        int bx0 = min(max((int)floorf(minx) - 1, 0) & ~1, 254);
        int bx1 = min(max((int)floorf(maxx) + 2, bx0), 255);
        int by0 = min(max((int)floorf(miny) - 1, 0), 255);
        int by1 = min(max((int)floorf(maxy) + 2, by0), 255);
        int rw  = bx1 - bx0 + 1;            // in [1, 49]
        int rh  = by1 - by0 + 1;            // in [1, 48]
        int rws = rw | 1;

        bool fastp = (minx > 1.0f) && (maxx < 253.0f) && (miny > 1.0f) && (maxy < 253.0f);

        int lx = tid & 31, lr = tid >> 5;
        const float* p0 = img + ((bi + 0) << 16);
        const float* p1 = img + ((bi + 1) << 16);
        const float* p2 = img + ((bi + 2) << 16);
        int npair = rw >> 1;
        for (int ry = lr; ry < rh; ry += 8) {
            int go = ((by0 + ry) << 8) + bx0;
            int so = ry * rws;
            if (lx < npair) {
                int c2x = lx << 1;
                float2 a = *(const float2*)(p0 + go + c2x);
                float2 c = *(const float2*)(p1 + go + c2x);
                float2 d = *(const float2*)(p2 + go + c2x);
                s01[so + c2x]     = make_float2(a.x, c.x);
                s01[so + c2x + 1] = make_float2(a.y, c.y);
                s2[so + c2x]     = d.x;
                s2[so + c2x + 1] = d.y;
            } else if (lx == npair && (rw & 1)) {
                int cx = rw - 1;
                s01[so + cx] = make_float2(p0[go + cx], p1[go + cx]);
                s2[so + cx]  = p2[go + cx];
            }
        }
        __syncthreads();

        int xg = tx0 + ((tid & 7) << 2);
        int y  = ty0 + (tid >> 3);
        float yn = (float)(2 * y + 1) * (1.0f / 256.0f) - 1.0f;
        float Wyv = g_Wy[(b << 8) + y];
        const float* Wxrow = g_Wx + (b << 8);
        float wsum = 0.0f;
        float vc0[4], vc1[4], vc2[4];

        float dix = cth * xsg;
        float diy = sth * xsg;
        float xn0 = ((float)(2 * xg + 1) * (1.0f / 256.0f) - 1.0f) * xsg;
        float xp0 = cth * xn0 - sth * yn;
        float yp0 = sth * xn0 + cth * yn;
        float ix = ((xp0 + 1.0f) * 256.0f - 1.0f) * 0.5f;
        float iy = ((yp0 + 1.0f) * 256.0f - 1.0f) * 0.5f;

        if (fastp) {
            #pragma unroll
            for (int k = 0; k < 4; k++) {
                float x0f = floorf(ix), y0f = floorf(iy);
                float wx = ix - x0f, wy = iy - y0f;
                float w00 = (1.0f - wy) * (1.0f - wx);
                float w01 = (1.0f - wy) * wx;
                float w10 = wy * (1.0f - wx);
                float w11 = wy * wx;

                int i00 = ((int)y0f - by0) * rws + ((int)x0f - bx0);
                int i10 = i00 + rws;

                float2 a00 = s01[i00], a01 = s01[i00 + 1];
                float2 a10 = s01[i10], a11 = s01[i10 + 1];
                float v0 = w00 * a00.x + w01 * a01.x + w10 * a10.x + w11 * a11.x;
                float v1 = w00 * a00.y + w01 * a01.y + w10 * a10.y + w11 * a11.y;
                float v2 = w00 * s2[i00] + w01 * s2[i00 + 1]
                         + w10 * s2[i10] + w11 * s2[i10 + 1];
                vc0[k] = v0; vc1[k] = v1; vc2[k] = v2;
                float s3 = v0; s3 += v1; s3 += v2;
                wsum += Wyv * Wxrow[xg + k] * s3;
                ix += dix;  iy += diy;
            }
        } else {
            #pragma unroll
            for (int k = 0; k < 4; k++) {
                float x0f = floorf(ix), y0f = floorf(iy);
                float wx = ix - x0f, wy = iy - y0f;
                int xi = (int)x0f, yi = (int)y0f;

                float w00 = (1.0f - wy) * (1.0f - wx);
                float w01 = (1.0f - wy) * wx;
                float w10 = wy * (1.0f - wx);
                float w11 = wy * wx;

                bool vx0 = (x0f >= 0.0f)  && (x0f <= 255.0f);
                bool vx1 = (x0f >= -1.0f) && (x0f <= 254.0f);
                bool vy0 = (y0f >= 0.0f)  && (y0f <= 255.0f);
                bool vy1 = (y0f >= -1.0f) && (y0f <= 254.0f);
                if (!(vy0 && vx0)) w00 = 0.0f;
                if (!(vy0 && vx1)) w01 = 0.0f;
                if (!(vy1 && vx0)) w10 = 0.0f;
                if (!(vy1 && vx1)) w11 = 0.0f;

                int xx0 = min(max(xi,     bx0), bx1) - bx0;
                int xx1 = min(max(xi + 1, bx0), bx1) - bx0;
                int yy0 = min(max(yi,     by0), by1) - by0;
                int yy1 = min(max(yi + 1, by0), by1) - by0;
                int i00 = yy0 * rws + xx0, i01 = yy0 * rws + xx1;
                int i10 = yy1 * rws + xx0, i11 = yy1 * rws + xx1;

                float2 a00 = s01[i00], a01 = s01[i01];
                float2 a10 = s01[i10], a11 = s01[i11];
                float v0 = w00 * a00.x + w01 * a01.x + w10 * a10.x + w11 * a11.x;
                float v1 = w00 * a00.y + w01 * a01.y + w10 * a10.y + w11 * a11.y;
                float v2 = w00 * s2[i00] + w01 * s2[i01]
                         + w10 * s2[i10] + w11 * s2[i11];
                vc0[k] = v0; vc1[k] = v1; vc2[k] = v2;
                float s3 = v0; s3 += v1; s3 += v2;
                wsum += Wyv * Wxrow[xg + k] * s3;
                ix += dix;  iy += diy;
            }
        }

        {
            __half2 a = __floats2half2_rn(vc0[0], vc0[1]);
            __half2 c2 = __floats2half2_rn(vc0[2], vc0[3]);
            *(uint2*)(g_buf + ((bi + 0) << 16) + (y << 8) + xg) =
                make_uint2(*(unsigned*)&a, *(unsigned*)&c2);
        }
        {
            __half2 a = __floats2half2_rn(vc1[0], vc1[1]);
            __half2 c2 = __floats2half2_rn(vc1[2], vc1[3]);
            *(uint2*)(g_buf + ((bi + 1) << 16) + (y << 8) + xg) =
                make_uint2(*(unsigned*)&a, *(unsigned*)&c2);
        }
        {
            __half2 a = __floats2half2_rn(vc2[0], vc2[1]);
            __half2 c2 = __floats2half2_rn(vc2[2], vc2[3]);
            *(uint2*)(g_buf + ((bi + 2) << 16) + (y << 8) + xg) =
                make_uint2(*(unsigned*)&a, *(unsigned*)&c2);
        }

        // block reduction, then release this tile's completion
        #pragma unroll
        for (int o = 16; o > 0; o >>= 1) wsum += __shfl_down_sync(0xffffffffu, wsum, o);
        if ((tid & 31) == 0) red[tid >> 5] = wsum;
        __threadfence();            // all threads: buf stores globally visible
        __syncthreads();
        if (tid == 0) {
            float v = red[0];
            #pragma unroll
            for (int i = 1; i < 8; i++) v += red[i];
            g_partial[(b << 6) + tile] = v;
            __threadfence();        // partial visible before counter bump
            atomicAdd(&g_done[b], 1);
        }
    } else {
        // ================= k2: crop resample + color pipeline ==============
        float* s = (float*)smraw;                       // 3840 floats
        float* sMean = (float*)(smraw + 15360);

        // wait for all 64 k1 tiles of this image (acquire)
        if (tid == 0) {
            unsigned ns = 64;
            while (true) {
                int d;
                asm volatile("ld.acquire.gpu.global.s32 %0, [%1];"
                             : "=r"(d) : "l"(&g_done[b]) : "memory");
                if (d == 64) break;
                __nanosleep(ns);
                if (ns < 4096) ns <<= 1;
            }
        }
        __syncthreads();

        int y0 = tile << 2;

        // warp 0: reduce the 64 per-tile partials of this image
        if (tid < 32) {
            float v = g_partial[(b << 6) + tid] + g_partial[(b << 6) + 32 + tid];
            #pragma unroll
            for (int o = 16; o > 0; o >>= 1) v += __shfl_down_sync(0xffffffffu, v, o);
            if (tid == 0) *sMean = v * (1.0f / (3.0f * 65536.0f));
        }

        int ybase = g_cy0[(b << 8) + y0];

        #pragma unroll
        for (int c = 0; c < 3; c++) {
            const __half* p = g_buf + ((bi + c) << 16);
            float* sc = s + c * 1280;
            #pragma unroll
            for (int i = tid; i < 640; i += 256) {
                int r = i >> 7, col = i & 127;
                __half2 h = *(const __half2*)(p + (min(ybase + r, 255) << 8) + (col << 1));
                *(float2*)&sc[(r << 8) + (col << 1)] = __half22float2(h);
            }
        }
        __syncthreads();

        int x4 = (tid & 63) << 2;
        int y  = y0 + (tid >> 6);

        int   iy0 = g_cy0[(b << 8) + y];
        float fy  = g_cfy[(b << 8) + y];
        int   ly0 = iy0 - ybase;        // in [0,3]
        float omfy = 1.0f - fy;

        float delta = (rdelta[b] * 2.0f - 1.0f) * 0.3f;
        float mag1  = (rm1[b]   * 2.0f - 1.0f) * 0.3f + 1.0f;
        float mag2  = (rm2[b]   * 2.0f - 1.0f) * 0.3f + 1.0f;
        float M = *sMean + delta;       // global mean + delta (exact identity)

        int r0 = ly0 << 8, r1 = (ly0 + 1) << 8;

        float4 o0v, o1v, o2v;
        float* o0p = &o0v.x; float* o1p = &o1v.x; float* o2p = &o2v.x;

        #pragma unroll
        for (int k = 0; k < 4; k++) {
            int x = x4 + k;
            int   xi0 = g_cx0[(b << 8) + x];
            float fx  = g_cfx[(b << 8) + x];
            int   xi1 = min(xi0 + 1, 255);

            float w00 = omfy * (1.0f - fx);
            float w01 = omfy * fx;
            float w10 = fy * (1.0f - fx);
            float w11 = fy * fx;

            float v0, v1, v2;
            {
                const float* sc = s;
                v0 = w00 * sc[r0 + xi0] + w01 * sc[r0 + xi1]
                   + w10 * sc[r1 + xi0] + w11 * sc[r1 + xi1] + delta;
            }
            {
                const float* sc = s + 1280;
                v1 = w00 * sc[r0 + xi0] + w01 * sc[r0 + xi1]
                   + w10 * sc[r1 + xi0] + w11 * sc[r1 + xi1] + delta;
            }
            {
                const float* sc = s + 2560;
                v2 = w00 * sc[r0 + xi0] + w01 * sc[r0 + xi1]
                   + w10 * sc[r1 + xi0] + w11 * sc[r1 + xi1] + delta;
            }
            float m = (v0 + v1 + v2) / 3.0f;

            o0p[k] = ((v0 - m) * mag1 + m - M) * mag2 + M;
            o1p[k] = ((v1 - m) * mag1 + m - M) * mag2 + M;
            o2p[k] = ((v2 - m) * mag1 + m - M) * mag2 + M;
        }

        int base = (y << 8) + x4;
        *(float4*)(out + ((bi + 0) << 16) + base) = o0v;
        *(float4*)(out + ((bi + 1) << 16) + base) = o1v;
        *(float4*)(out + ((bi + 2) << 16) + base) = o2v;
    }
}

// ---------------------------------------------------------------------------
extern "C" void kernel_launch(void* const* d_in, const int* in_sizes, int n_in,
                              void* d_out, int out_size)
{
    const float* img = (const float*)d_in[0];
    const float* rt  = (const float*)d_in[1];
    const float* rf  = (const float*)d_in[2];
    const float* rsz = (const float*)d_in[3];
    const float* rsh = (const float*)d_in[4];
    const float* rd  = (const float*)d_in[5];
    const float* rm1 = (const float*)d_in[6];
    const float* rm2 = (const float*)d_in[7];
    float* out = (float*)d_out;

    k0_params<<<Bn, 256>>>(rt, rf, rsz, rsh);
    kmain<<<128 * 256, 256>>>(img, rd, rm1, rm2, out);
}

// round 14
// speedup vs baseline: 1.3901x; 1.3901x over previous
#include <cuda_runtime.h>
#include <cuda_fp16.h>

#define Bn 256
#define Cn 3
#define Hn 256
#define Wn 256

// Scratch (static device globals — allocation-free per harness rules)
__device__ __half g_buf[Bn * Cn * Hn * Wn]; // rotated+flipped intermediate (fp16, 96 MiB)
__device__ float g_Wy[Bn * Hn];             // per-batch crop row weight vectors
__device__ float g_Wx[Bn * Wn];
__device__ int   g_cy0[Bn * Hn];            // crop mapping: floor coord + frac
__device__ float g_cfy[Bn * Hn];
__device__ int   g_cx0[Bn * Wn];
__device__ float g_cfx[Bn * Wn];
__device__ float g_cth[Bn], g_sth[Bn], g_xsign[Bn];
__device__ float g_partial[Bn * 64];        // per-block weighted partial sums

// ---------------------------------------------------------------------------
// K0: per-batch parameters. Wy/Wx built by PARALLEL windowed gather: the crop
// map is monotone with stride in (0.797, 1] and clipping never binds
// (start >= 0, start+255 <= sz-1), so bin t only receives from y with
// sy0[y] in {t-1, t} — a <=4-wide window; we scan 9 padded values in
// ascending y (bit-identical accumulation order to the serial scatter).
// ---------------------------------------------------------------------------
__global__ void __launch_bounds__(256) k0_params(
    const float* __restrict__ rt, const float* __restrict__ rf,
    const float* __restrict__ rsz, const float* __restrict__ rsh)
{
    int b = blockIdx.x;
    int t = threadIdx.x;

    __shared__ float s_start[2], s_sizem1[2];
    __shared__ int   sy0[256];  __shared__ float sfy[256];
    __shared__ int   sx0[256];  __shared__ float sfx[256];

    if (t == 0) {
        float th = (rt[b] * 2.0f - 1.0f) * 3.14159265358979323846f;
        g_cth[b] = cosf(th);
        g_sth[b] = sinf(th);
        g_xsign[b] = (rf[b] > 0.5f) ? -1.0f : 1.0f;
    }
    if (t < 2) {
        // sizes = round(h*(r/4+1) - 0.5); *256 exact, no contraction risk
        float r  = rsz[b * 2 + t];
        float sz = rintf((r * 0.25f + 1.0f) * 256.0f - 0.5f);
        float maxsh = sz - 256.0f;
        float rng   = maxsh - 1e-5f;
        // shifts = round(rand*rng - rng/2); forbid fma contraction (round edge)
        float sh = rintf(__fsub_rn(__fmul_rn(rsh[b * 2 + t], rng), rng * 0.5f));
        s_start[t]  = floorf(maxsh * 0.5f) + sh;
        s_sizem1[t] = sz - 1.0f;
    }
    __syncthreads();

    {
        float sy = __fdiv_rn(__fmul_rn(s_start[0] + (float)t, 255.0f), s_sizem1[0]);
        sy = fminf(fmaxf(sy, 0.0f), 255.0f);
        float y0 = floorf(sy);
        sy0[t] = (int)y0;  sfy[t] = sy - y0;

        float sx = __fdiv_rn(__fmul_rn(s_start[1] + (float)t, 255.0f), s_sizem1[1]);
        sx = fminf(fmaxf(sx, 0.0f), 255.0f);
        float x0 = floorf(sx);
        sx0[t] = (int)x0;  sfx[t] = sx - x0;
    }
    __syncthreads();

    float Wy = 0.0f;
    {
        float base = (float)(t - 1) * s_sizem1[0] * (1.0f / 255.0f) - s_start[0];
        int yl = max((int)floorf(base) - 2, 0);
        int yh = min(yl + 8, 255);
        for (int y = yl; y <= yh; y++) {
            int i = sy0[y]; float f = sfy[y];
            if (i == t - 1) Wy += f;
            if (i == t)     Wy += 1.0f - f;
        }
    }
    float Wx = 0.0f;
    {
        float base = (float)(t - 1) * s_sizem1[1] * (1.0f / 255.0f) - s_start[1];
        int xl = max((int)floorf(base) - 2, 0);
        int xh = min(xl + 8, 255);
        for (int x = xl; x <= xh; x++) {
            int i = sx0[x]; float f = sfx[x];
            if (i == t - 1) Wx += f;
            if (i == t)     Wx += 1.0f - f;
        }
    }

    int o = (b << 8) + t;
    g_cy0[o] = sy0[t];  g_cfy[o] = sfy[t];
    g_cx0[o] = sx0[t];  g_cfx[o] = sfx[t];
    g_Wy[o]  = Wy;      g_Wx[o]  = Wx;
}

// ---------------------------------------------------------------------------
// K1: rotation + flip + zero-pad -> fp16 buf. Monolithic (one launch).
// Channel-interleaved smem (float2 for ch0/ch1, float for ch2): bilinear taps
// for two channels are single LDS.64. Interior tiles take a fast path with no
// validity predicates or clamps. Accumulates the crop-weighted sum.
// ---------------------------------------------------------------------------
__global__ void __launch_bounds__(256) k1_rotate(const float* __restrict__ img)
{
    __shared__ float2 s01[2352];    // (49 stride x 48 rows) ch0/ch1 pairs, 18.4 KB
    __shared__ float  s2[2352];     // ch2, 9.2 KB
    __shared__ float  red[8];

    int blk  = blockIdx.x;
    int b    = blk >> 6;
    int tile = blk & 63;
    int tx0  = (tile & 7) << 5;
    int ty0  = (tile >> 3) << 5;
    int tid  = threadIdx.x;

    float cth = g_cth[b], sth = g_sth[b], xsg = g_xsign[b];

    // bounding box of the rotated tile (linear map -> extremes at corners)
    float minx = 1e30f, maxx = -1e30f, miny = 1e30f, maxy = -1e30f;
    {
        float xnA = ((float)(2 * tx0 + 1)        * (1.0f / 256.0f) - 1.0f) * xsg;
        float xnB = ((float)(2 * (tx0 + 31) + 1) * (1.0f / 256.0f) - 1.0f) * xsg;
        float ynA =  (float)(2 * ty0 + 1)        * (1.0f / 256.0f) - 1.0f;
        float ynB =  (float)(2 * (ty0 + 31) + 1) * (1.0f / 256.0f) - 1.0f;
        #pragma unroll
        for (int i = 0; i < 4; i++) {
            float xn = (i & 1) ? xnB : xnA;
            float yn = (i & 2) ? ynB : ynA;
            float xp = cth * xn - sth * yn;
            float yp = sth * xn + cth * yn;
            float ix = ((xp + 1.0f) * 256.0f - 1.0f) * 0.5f;
            float iy = ((yp + 1.0f) * 256.0f - 1.0f) * 0.5f;
            minx = fminf(minx, ix); maxx = fmaxf(maxx, ix);
            miny = fminf(miny, iy); maxy = fmaxf(maxy, iy);
        }
    }
    // bbox clamped into image (BOTH ends — off-image tiles otherwise produce
    // bx0 > 255 and a negative rw), bx0 forced even (float2 gmem alignment),
    // non-degenerate (rw,rh >= 1).
    int bx0 = min(max((int)floorf(minx) - 1, 0) & ~1, 254); // even, in [0,254]
    int bx1 = min(max((int)floorf(maxx) + 2, bx0), 255);
    int by0 = min(max((int)floorf(miny) - 1, 0), 255);
    int by1 = min(max((int)floorf(maxy) + 2, by0), 255);
    int rw  = bx1 - bx0 + 1;            // in [1, 49]
    int rh  = by1 - by0 + 1;            // in [1, 48]
    int rws = rw | 1;                   // odd stride, <= 49

    bool fast = (minx > 1.0f) && (maxx < 253.0f) && (miny > 1.0f) && (maxy < 253.0f);

    // stage footprint: 32 lanes x 8 rows per pass, float2 gmem loads
    int lx = tid & 31, lr = tid >> 5;
    int bi = b * 3;
    const float* p0 = img + ((bi + 0) << 16);
    const float* p1 = img + ((bi + 1) << 16);
    const float* p2 = img + ((bi + 2) << 16);
    int npair = rw >> 1;
    for (int ry = lr; ry < rh; ry += 8) {
        int go = ((by0 + ry) << 8) + bx0;
        int so = ry * rws;
        if (lx < npair) {
            int c2x = lx << 1;
            float2 a = *(const float2*)(p0 + go + c2x);
            float2 c = *(const float2*)(p1 + go + c2x);
            float2 d = *(const float2*)(p2 + go + c2x);
            s01[so + c2x]     = make_float2(a.x, c.x);
            s01[so + c2x + 1] = make_float2(a.y, c.y);
            s2[so + c2x]     = d.x;
            s2[so + c2x + 1] = d.y;
        } else if (lx == npair && (rw & 1)) {
            int cx = rw - 1;
            s01[so + cx] = make_float2(p0[go + cx], p1[go + cx]);
            s2[so + cx]  = p2[go + cx];
        }
    }
    __syncthreads();

    // compute: 4 consecutive x per thread; ix,iy advance affinely per x-step
    int xg = tx0 + ((tid & 7) << 2);
    int y  = ty0 + (tid >> 3);
    float yn = (float)(2 * y + 1) * (1.0f / 256.0f) - 1.0f;
    float Wyv = g_Wy[(b << 8) + y];
    const float* Wxrow = g_Wx + (b << 8);
    float wsum = 0.0f;
    float vc0[4], vc1[4], vc2[4];

    float dix = cth * xsg;
    float diy = sth * xsg;
    float xn0 = ((float)(2 * xg + 1) * (1.0f / 256.0f) - 1.0f) * xsg;
    float xp0 = cth * xn0 - sth * yn;
    float yp0 = sth * xn0 + cth * yn;
    float ix = ((xp0 + 1.0f) * 256.0f - 1.0f) * 0.5f;
    float iy = ((yp0 + 1.0f) * 256.0f - 1.0f) * 0.5f;

    if (fast) {
        // all taps valid & unclamped: xi in [1,253], yi in [1,253]
        #pragma unroll
        for (int k = 0; k < 4; k++) {
            float x0f = floorf(ix), y0f = floorf(iy);
            float wx = ix - x0f, wy = iy - y0f;
            float w00 = (1.0f - wy) * (1.0f - wx);
            float w01 = (1.0f - wy) * wx;
            float w10 = wy * (1.0f - wx);
            float w11 = wy * wx;

            int i00 = ((int)y0f - by0) * rws + ((int)x0f - bx0);
            int i10 = i00 + rws;

            float2 a00 = s01[i00], a01 = s01[i00 + 1];
            float2 a10 = s01[i10], a11 = s01[i10 + 1];
            float v0 = w00 * a00.x + w01 * a01.x + w10 * a10.x + w11 * a11.x;
            float v1 = w00 * a00.y + w01 * a01.y + w10 * a10.y + w11 * a11.y;
            float v2 = w00 * s2[i00] + w01 * s2[i00 + 1]
                     + w10 * s2[i10] + w11 * s2[i10 + 1];
            vc0[k] = v0; vc1[k] = v1; vc2[k] = v2;
            float s3 = v0; s3 += v1; s3 += v2;
            wsum += Wyv * Wxrow[xg + k] * s3;
            ix += dix;  iy += diy;
        }
    } else {
        #pragma unroll
        for (int k = 0; k < 4; k++) {
            float x0f = floorf(ix), y0f = floorf(iy);
            float wx = ix - x0f, wy = iy - y0f;
            int xi = (int)x0f, yi = (int)y0f;

            float w00 = (1.0f - wy) * (1.0f - wx);
            float w01 = (1.0f - wy) * wx;
            float w10 = wy * (1.0f - wx);
            float w11 = wy * wx;

            bool vx0 = (x0f >= 0.0f)  && (x0f <= 255.0f);
            bool vx1 = (x0f >= -1.0f) && (x0f <= 254.0f);
            bool vy0 = (y0f >= 0.0f)  && (y0f <= 255.0f);
            bool vy1 = (y0f >= -1.0f) && (y0f <= 254.0f);
            if (!(vy0 && vx0)) w00 = 0.0f;
            if (!(vy0 && vx1)) w01 = 0.0f;
            if (!(vy1 && vx0)) w10 = 0.0f;
            if (!(vy1 && vx1)) w11 = 0.0f;

            // clamp taps INTO the staged bbox: always valid smem index; equals
            // the [0,255] clamp whenever the corresponding weight is nonzero.
            int xx0 = min(max(xi,     bx0), bx1) - bx0;
            int xx1 = min(max(xi + 1, bx0), bx1) - bx0;
            int yy0 = min(max(yi,     by0), by1) - by0;
            int yy1 = min(max(yi + 1, by0), by1) - by0;
            int i00 = yy0 * rws + xx0, i01 = yy0 * rws + xx1;
            int i10 = yy1 * rws + xx0, i11 = yy1 * rws + xx1;

            float2 a00 = s01[i00], a01 = s01[i01];
            float2 a10 = s01[i10], a11 = s01[i11];
            float v0 = w00 * a00.x + w01 * a01.x + w10 * a10.x + w11 * a11.x;
            float v1 = w00 * a00.y + w01 * a01.y + w10 * a10.y + w11 * a11.y;
            float v2 = w00 * s2[i00] + w01 * s2[i01]
                     + w10 * s2[i10] + w11 * s2[i11];
            vc0[k] = v0; vc1[k] = v1; vc2[k] = v2;
            float s3 = v0; s3 += v1; s3 += v2;
            wsum += Wyv * Wxrow[xg + k] * s3;
            ix += dix;  iy += diy;
        }
    }

    // pack 4 floats -> 2 half2 -> one 8B store per channel
    {
        __half2 a = __floats2half2_rn(vc0[0], vc0[1]);
        __half2 c2 = __floats2half2_rn(vc0[2], vc0[3]);
        *(uint2*)(g_buf + ((bi + 0) << 16) + (y << 8) + xg) =
            make_uint2(*(unsigned*)&a, *(unsigned*)&c2);
    }
    {
        __half2 a = __floats2half2_rn(vc1[0], vc1[1]);
        __half2 c2 = __floats2half2_rn(vc1[2], vc1[3]);
        *(uint2*)(g_buf + ((bi + 1) << 16) + (y << 8) + xg) =
            make_uint2(*(unsigned*)&a, *(unsigned*)&c2);
    }
    {
        __half2 a = __floats2half2_rn(vc2[0], vc2[1]);
        __half2 c2 = __floats2half2_rn(vc2[2], vc2[3]);
        *(uint2*)(g_buf + ((bi + 2) << 16) + (y << 8) + xg) =
            make_uint2(*(unsigned*)&a, *(unsigned*)&c2);
    }

    // block reduction: full-warp shuffles, then thread 0 sums 8 warp partials
    #pragma unroll
    for (int o = 16; o > 0; o >>= 1) wsum += __shfl_down_sync(0xffffffffu, wsum, o);
    if ((tid & 31) == 0) red[tid >> 5] = wsum;
    __syncthreads();
    if (tid == 0) {
        float v = red[0];
        #pragma unroll
        for (int i = 1; i < 8; i++) v += red[i];
        g_partial[(b << 6) + tile] = v;
    }
}

// ---------------------------------------------------------------------------
// K2: separable crop resample from fp16 buf + full color pipeline. Monolithic.
// Block = 4 output rows x 256 cols; stages 5 source rows (fp32-converted) in
// smem with aligned float2 stores. Warp 0 reduces this image's 64 k1-partials
// to the global mean in-block. float4 output stores.
// ---------------------------------------------------------------------------
__global__ void __launch_bounds__(256) k2_crop_color(
    const float* __restrict__ rdelta, const float* __restrict__ rm1,
    const float* __restrict__ rm2, float* __restrict__ out)
{
    __shared__ float s[3 * 5 * 256];    // 15 KB
    __shared__ float sMean;

    int blk  = blockIdx.x;
    int b    = blk >> 6;
    int tile = blk & 63;
    int y0   = tile << 2;
    int tid  = threadIdx.x;
    int bi   = b * 3;

    // warp 0: reduce the 64 per-block partials of this image
    if (tid < 32) {
        float v = g_partial[(b << 6) + tid] + g_partial[(b << 6) + 32 + tid];
        #pragma unroll
        for (int o = 16; o > 0; o >>= 1) v += __shfl_down_sync(0xffffffffu, v, o);
        if (tid == 0) sMean = v * (1.0f / (3.0f * 65536.0f));
    }

    int ybase = g_cy0[(b << 8) + y0];

    // stage 5 rows x 3 ch, half2 -> float2 (aligned smem stores)
    #pragma unroll
    for (int c = 0; c < 3; c++) {
        const __half* p = g_buf + ((bi + c) << 16);
        float* sc = s + c * 1280;
        #pragma unroll
        for (int i = tid; i < 640; i += 256) {
            int r = i >> 7, col = i & 127;          // 128 half2 per row
            __half2 h = *(const __half2*)(p + (min(ybase + r, 255) << 8) + (col << 1));
            *(float2*)&sc[(r << 8) + (col << 1)] = __half22float2(h);
        }
    }
    __syncthreads();

    int x4 = (tid & 63) << 2;
    int y  = y0 + (tid >> 6);

    int   iy0 = g_cy0[(b << 8) + y];
    float fy  = g_cfy[(b << 8) + y];
    int   ly0 = iy0 - ybase;        // in [0,3]
    float omfy = 1.0f - fy;

    float delta = (rdelta[b] * 2.0f - 1.0f) * 0.3f;
    float mag1  = (rm1[b]   * 2.0f - 1.0f) * 0.3f + 1.0f;
    float mag2  = (rm2[b]   * 2.0f - 1.0f) * 0.3f + 1.0f;
    float M = sMean + delta;        // global mean + delta (exact identity)

    int r0 = ly0 << 8, r1 = (ly0 + 1) << 8;

    float4 o0v, o1v, o2v;
    float* o0p = &o0v.x; float* o1p = &o1v.x; float* o2p = &o2v.x;

    #pragma unroll
    for (int k = 0; k < 4; k++) {
        int x = x4 + k;
        int   xi0 = g_cx0[(b << 8) + x];
        float fx  = g_cfx[(b << 8) + x];
        int   xi1 = min(xi0 + 1, 255);

        float w00 = omfy * (1.0f - fx);
        float w01 = omfy * fx;
        float w10 = fy * (1.0f - fx);
        float w11 = fy * fx;

        float v0, v1, v2;
        {
            const float* sc = s;
            v0 = w00 * sc[r0 + xi0] + w01 * sc[r0 + xi1]
               + w10 * sc[r1 + xi0] + w11 * sc[r1 + xi1] + delta;
        }
        {
            const float* sc = s + 1280;
            v1 = w00 * sc[r0 + xi0] + w01 * sc[r0 + xi1]
               + w10 * sc[r1 + xi0] + w11 * sc[r1 + xi1] + delta;
        }
        {
            const float* sc = s + 2560;
            v2 = w00 * sc[r0 + xi0] + w01 * sc[r0 + xi1]
               + w10 * sc[r1 + xi0] + w11 * sc[r1 + xi1] + delta;
        }
        float m = (v0 + v1 + v2) / 3.0f;

        o0p[k] = ((v0 - m) * mag1 + m - M) * mag2 + M;
        o1p[k] = ((v1 - m) * mag1 + m - M) * mag2 + M;
        o2p[k] = ((v2 - m) * mag1 + m - M) * mag2 + M;
    }

    int base = (y << 8) + x4;
    *(float4*)(out + ((bi + 0) << 16) + base) = o0v;
    *(float4*)(out + ((bi + 1) << 16) + base) = o1v;
    *(float4*)(out + ((bi + 2) << 16) + base) = o2v;
}

// ---------------------------------------------------------------------------
extern "C" void kernel_launch(void* const* d_in, const int* in_sizes, int n_in,
                              void* d_out, int out_size)
{
    const float* img = (const float*)d_in[0];
    const float* rt  = (const float*)d_in[1];
    const float* rf  = (const float*)d_in[2];
    const float* rsz = (const float*)d_in[3];
    const float* rsh = (const float*)d_in[4];
    const float* rd  = (const float*)d_in[5];
    const float* rm1 = (const float*)d_in[6];
    const float* rm2 = (const float*)d_in[7];
    float* out = (float*)d_out;

    k0_params<<<Bn, 256>>>(rt, rf, rsz, rsh);
    k1_rotate<<<Bn * 64, 256>>>(img);
    k2_crop_color<<<Bn * 64, 256>>>(rd, rm1, rm2, out);
}